// round 9
// baseline (speedup 1.0000x reference)
#include <cuda_runtime.h>
#include <math.h>

// ---------------------------------------------------------------------------
// N=3072 all-pairs mask/bucket kernel.
// Out sections (float32, concatenated): dxyz (N,N,3), buckets (N,N),
// dscanid (N,N), mask (N,N).
//
// R7 -> R8: revert __stcs (evict-first defeated L2 write-residency across
// graph replays: DRAM% and issue% both dropped in every __stcs round) and
// revert SIMD two-word meta (extra load, no dur win). Back to R3 base:
// single float4 meta load, scalar compares, plain stores. New: branchless
// threshold-based bucket (logf eliminated -> no MUFU, no divergence; sup is
// an integer in [-6,2], equal to 2 - #{m: xa > 2^((m+1.5)/2)}).
// ---------------------------------------------------------------------------

#define MAXN 8192
__device__ float4 g_P[MAXN];   // {x, y, z, packed_meta}

// packed_meta bits: [0:3) batch, [3:6) block, [6:9) c0, [9:12) c1, [12:15) c2,
//                   [15:20) xy_coarse0+16, [20:25) xy_coarse1+16
__global__ void pack_kernel(const float* __restrict__ xyz,
                            const int*   __restrict__ grid, int N) {
    int i = blockIdx.x * blockDim.x + threadIdx.x;
    if (i >= N) return;
    float x = xyz[3*i+0], y = xyz[3*i+1], z = xyz[3*i+2];
    int batch = grid[5*i+0], blk = grid[5*i+1];
    int c0 = grid[5*i+2], c1 = grid[5*i+3], c2 = grid[5*i+4];
    // xy_coarse = ceil(xyz[:, :2] / 3.0)  — pinned IEEE division
    int xc0 = (int)ceilf(__fdiv_rn(x, 3.0f));
    int xc1 = (int)ceilf(__fdiv_rn(y, 3.0f));
    unsigned meta = (unsigned)(batch & 7)
                  | ((unsigned)(blk   & 7)        << 3)
                  | ((unsigned)(c0    & 7)        << 6)
                  | ((unsigned)(c1    & 7)        << 9)
                  | ((unsigned)(c2    & 7)        << 12)
                  | ((unsigned)((xc0 + 16) & 31)  << 15)
                  | ((unsigned)((xc1 + 16) & 31)  << 20);
    g_P[i] = make_float4(x, y, z, __uint_as_float(meta));
}

// bucket_base minus BETA: integer-valued float v, reference value = 8 + v.
// Branchless: fine path rintf(x); coarse path via 8 threshold compares
// (T_m = 2^((m+1.5)/2), m=1..8) replacing round(2 - 6*log8(xa/2)).
__device__ __forceinline__ float bucket_v(float d) {
    float x  = d * 2.0f;            // x / RES, RES = 0.5 (exact)
    float xa = fabsf(x);
    float fine = rintf(x);          // round-half-even == jnp.round
    float cnt = 0.0f;
    cnt += (xa > 2.3784142300054420f) ? 1.0f : 0.0f;  // 2^1.25
    cnt += (xa > 3.3635856610148585f) ? 1.0f : 0.0f;  // 2^1.75
    cnt += (xa > 4.7568284600108841f) ? 1.0f : 0.0f;  // 2^2.25
    cnt += (xa > 6.7271713220297170f) ? 1.0f : 0.0f;  // 2^2.75
    cnt += (xa > 9.5136569200217682f) ? 1.0f : 0.0f;  // 2^3.25
    cnt += (xa > 13.454342644059434f) ? 1.0f : 0.0f;  // 2^3.75
    cnt += (xa > 19.027313840043536f) ? 1.0f : 0.0f;  // 2^4.25
    cnt += (xa > 26.908685288118868f) ? 1.0f : 0.0f;  // 2^4.75
    float sup = 2.0f - cnt;                           // in [-6, 2]
    float coarse = (x > 0.0f) ? sup : -sup;           // sign(x) * sup
    return (xa <= 2.0f) ? fine : coarse;
}

__global__ __launch_bounds__(256)
void pair_kernel(float* __restrict__ out, int N) {
    int i  = blockIdx.y;
    int j0 = (blockIdx.x * blockDim.x + threadIdx.x) * 4;
    if (j0 >= N) return;
    int nvalid = (N - j0 < 4) ? (N - j0) : 4;

    float4 pi = g_P[i];
    unsigned mi = __float_as_uint(pi.w);
    int bi  = (mi >> 3)  & 7;
    int ci0 = (mi >> 6)  & 7, ci1 = (mi >> 9) & 7, ci2 = (mi >> 12) & 7;
    int xi0 = (mi >> 15) & 31, xi1 = (mi >> 20) & 31;
    int si  = bi >> 1;   // scanid_i

    float dxs[12];
    float bks[4], dss[4], mks[4];

#pragma unroll
    for (int t = 0; t < 4; t++) {
        if (t >= nvalid) {
            dxs[3*t] = dxs[3*t+1] = dxs[3*t+2] = 0.f;
            bks[t] = dss[t] = mks[t] = 0.f;
            continue;
        }
        int j = j0 + t;
        float4 pj = g_P[j];
        unsigned mj = __float_as_uint(pj.w);

        bool batch_eq = ((mi ^ mj) & 7u) == 0u;
        int  bj       = (mj >> 3) & 7;
        bool block_le = bi <= bj;

        int dc0 = ci0 - (int)((mj >> 6)  & 7);
        int dc1 = ci1 - (int)((mj >> 9)  & 7);
        int dc2 = ci2 - (int)((mj >> 12) & 7);
        bool coord_adj = (abs(dc0) <= 1) & (abs(dc1) <= 1) & (abs(dc2) <= 1);
        bool forcekeep = coord_adj & (bi == bj);

        int e0 = xi0 - (int)((mj >> 15) & 31);
        int e1 = xi1 - (int)((mj >> 20) & 31);
        bool keep_coarse = (abs(e0) <= 1) & (abs(e1) <= 1);

        float dx = pi.x - pj.x, dy = pi.y - pj.y, dz = pi.z - pj.z;
        bool keepr = (dx*dx + dy*dy + dz*dz) <= 9.0f;

        bool mask = batch_eq & block_le & (forcekeep | keep_coarse)
                                        & (forcekeep | keepr);

        dxs[3*t+0] = mask ? dx : 0.0f;
        dxs[3*t+1] = mask ? dy : 0.0f;
        dxs[3*t+2] = mask ? dz : 0.0f;

        // Branchless bucket + dscanid, select at the end (no divergence).
        int b = 289 * (8 + (int)bucket_v(dx))
              +  17 * (8 + (int)bucket_v(dy))
              +        (8 + (int)bucket_v(dz));
        int ds = (bj >> 1) - si;

        bks[t] = mask ? (float)b  : 0.0f;
        dss[t] = mask ? (float)ds : 0.0f;
        mks[t] = mask ? 1.0f      : 0.0f;
    }

    size_t NN  = (size_t)N * (size_t)N;
    size_t row = (size_t)i * (size_t)N + (size_t)j0;

    if (nvalid == 4) {
        float4* dp = reinterpret_cast<float4*>(out + row * 3);
        dp[0] = make_float4(dxs[0], dxs[1], dxs[2],  dxs[3]);
        dp[1] = make_float4(dxs[4], dxs[5], dxs[6],  dxs[7]);
        dp[2] = make_float4(dxs[8], dxs[9], dxs[10], dxs[11]);
        *reinterpret_cast<float4*>(out + 3*NN + row) = make_float4(bks[0], bks[1], bks[2], bks[3]);
        *reinterpret_cast<float4*>(out + 4*NN + row) = make_float4(dss[0], dss[1], dss[2], dss[3]);
        *reinterpret_cast<float4*>(out + 5*NN + row) = make_float4(mks[0], mks[1], mks[2], mks[3]);
    } else {
        for (int t = 0; t < nvalid; t++) {
            out[(row + t)*3 + 0] = dxs[3*t+0];
            out[(row + t)*3 + 1] = dxs[3*t+1];
            out[(row + t)*3 + 2] = dxs[3*t+2];
            out[3*NN + row + t] = bks[t];
            out[4*NN + row + t] = dss[t];
            out[5*NN + row + t] = mks[t];
        }
    }
}

extern "C" void kernel_launch(void* const* d_in, const int* in_sizes, int n_in,
                              void* d_out, int out_size) {
    const float* xyz  = (const float*)d_in[0];
    const int*   grid = (const int*)d_in[1];
    int N = in_sizes[0] / 3;
    float* out = (float*)d_out;

    pack_kernel<<<(N + 255) / 256, 256>>>(xyz, grid, N);

    dim3 g((N + 1023) / 1024, N);
    pair_kernel<<<g, 256>>>(out, N);
}

// round 12
// speedup vs baseline: 1.2855x; 1.2855x over previous
#include <cuda_runtime.h>
#include <math.h>

// ---------------------------------------------------------------------------
// N=3072 all-pairs mask/bucket kernel.
// Out sections (float32, concatenated): dxyz (N,N,3), buckets (N,N),
// dscanid (N,N), mask (N,N).
//
// R9 -> R10: back to R3 compute (divergent logf bucket path — mask is sparse
// and warp-coherent). New memory mapping: warp owns 128 consecutive j,
// thread t-loop handles j = base + 32t + lane.
//   * j loads contiguous per instr: 64 -> 16 wavefronts/warp-iter
//   * buckets/dscanid/mask: coalesced scalar stores
//   * dxyz staged via per-warp smem tile -> 3 contiguous float4 bursts
//     (36 -> 12 global wavefronts)
// ---------------------------------------------------------------------------

#define MAXN 8192
__device__ float4 g_P[MAXN];   // {x, y, z, packed_meta}

// packed_meta bits: [0:3) batch, [3:6) block, [6:9) c0, [9:12) c1, [12:15) c2,
//                   [15:20) xy_coarse0+16, [20:25) xy_coarse1+16
__global__ void pack_kernel(const float* __restrict__ xyz,
                            const int*   __restrict__ grid, int N) {
    int i = blockIdx.x * blockDim.x + threadIdx.x;
    if (i >= N) return;
    float x = xyz[3*i+0], y = xyz[3*i+1], z = xyz[3*i+2];
    int batch = grid[5*i+0], blk = grid[5*i+1];
    int c0 = grid[5*i+2], c1 = grid[5*i+3], c2 = grid[5*i+4];
    // xy_coarse = ceil(xyz[:, :2] / 3.0)  — pinned IEEE division
    int xc0 = (int)ceilf(__fdiv_rn(x, 3.0f));
    int xc1 = (int)ceilf(__fdiv_rn(y, 3.0f));
    unsigned meta = (unsigned)(batch & 7)
                  | ((unsigned)(blk   & 7)       << 3)
                  | ((unsigned)(c0    & 7)       << 6)
                  | ((unsigned)(c1    & 7)       << 9)
                  | ((unsigned)(c2    & 7)       << 12)
                  | ((unsigned)((xc0 + 16) & 31) << 15)
                  | ((unsigned)((xc1 + 16) & 31) << 20);
    g_P[i] = make_float4(x, y, z, __uint_as_float(meta));
}

// bucket_base minus BETA: integer-valued float v, reference value = 8 + v.
__device__ __forceinline__ float bucket_v(float d) {
    float x  = d * 2.0f;            // x / RES, RES = 0.5 (exact)
    float xa = fabsf(x);
    if (xa <= 2.0f) {
        return rintf(x);            // round-half-even == jnp.round
    } else {
        float lr  = logf(xa * 0.5f) * 0.48089834696298783f; // 1/ln(8)
        float sup = fminf(rintf(2.0f - 6.0f * lr), 8.0f);
        return (x > 0.0f) ? sup : -sup;
    }
}

__global__ __launch_bounds__(256)
void pair_kernel(float* __restrict__ out, int N) {
    __shared__ float sdx[8][384];      // per-warp dxyz staging (1.5 KB each)

    int warp = threadIdx.x >> 5;
    int lane = threadIdx.x & 31;
    int i    = blockIdx.y;
    int j0w  = blockIdx.x * 1024 + warp * 128;   // warp's 128-wide j base
    if (j0w >= N) return;
    bool full = (j0w + 128 <= N);

    float4 pi = g_P[i];
    unsigned mi = __float_as_uint(pi.w);
    int bi  = (mi >> 3)  & 7;
    int ci0 = (mi >> 6)  & 7, ci1 = (mi >> 9) & 7, ci2 = (mi >> 12) & 7;
    int xi0 = (mi >> 15) & 31, xi1 = (mi >> 20) & 31;
    int si  = bi >> 1;   // scanid_i

    size_t NN   = (size_t)N * (size_t)N;
    size_t rowb = (size_t)i * (size_t)N + (size_t)j0w;

#pragma unroll
    for (int t = 0; t < 4; t++) {
        int jl = t * 32 + lane;        // local j index within warp tile
        int j  = j0w + jl;
        bool inb = full | (j < N);
        float4 pj = g_P[inb ? j : 0];
        unsigned mj = __float_as_uint(pj.w);

        bool batch_eq = ((mi ^ mj) & 7u) == 0u;
        int  bj       = (mj >> 3) & 7;
        bool block_le = bi <= bj;

        int dc0 = ci0 - (int)((mj >> 6)  & 7);
        int dc1 = ci1 - (int)((mj >> 9)  & 7);
        int dc2 = ci2 - (int)((mj >> 12) & 7);
        bool coord_adj = (abs(dc0) <= 1) & (abs(dc1) <= 1) & (abs(dc2) <= 1);
        bool forcekeep = coord_adj & (bi == bj);

        int e0 = xi0 - (int)((mj >> 15) & 31);
        int e1 = xi1 - (int)((mj >> 20) & 31);
        bool keep_coarse = (abs(e0) <= 1) & (abs(e1) <= 1);

        float dx = pi.x - pj.x, dy = pi.y - pj.y, dz = pi.z - pj.z;
        bool keepr = (dx*dx + dy*dy + dz*dz) <= 9.0f;

        bool mask = batch_eq & block_le & (forcekeep | keep_coarse)
                                        & (forcekeep | keepr) & inb;

        // dxyz into per-warp smem tile (stride-3 words: conflict-free)
        sdx[warp][jl*3 + 0] = mask ? dx : 0.0f;
        sdx[warp][jl*3 + 1] = mask ? dy : 0.0f;
        sdx[warp][jl*3 + 2] = mask ? dz : 0.0f;

        // sparse, warp-coherent: divergent bucket path wins
        int b = 0, ds = 0;
        if (mask) {
            b = 289 * (8 + (int)bucket_v(dx))
              +  17 * (8 + (int)bucket_v(dy))
              +        (8 + (int)bucket_v(dz));
            ds = (bj >> 1) - si;
        }
        if (inb) {
            out[3*NN + rowb + jl] = (float)b;
            out[4*NN + rowb + jl] = (float)ds;
            out[5*NN + rowb + jl] = mask ? 1.0f : 0.0f;
        }
    }

    __syncwarp();

    // dxyz: 384 consecutive floats per warp -> 3 contiguous float4 bursts
    if (full) {
        const float4* src = reinterpret_cast<const float4*>(sdx[warp]);
        float4* dst = reinterpret_cast<float4*>(out + rowb * 3);
        dst[lane]      = src[lane];
        dst[lane + 32] = src[lane + 32];
        dst[lane + 64] = src[lane + 64];
    } else {
        int nrem = (N - j0w) * 3;      // floats in this partial tile
        for (int k = lane; k < nrem; k += 32)
            out[rowb * 3 + k] = sdx[warp][k];
    }
}

extern "C" void kernel_launch(void* const* d_in, const int* in_sizes, int n_in,
                              void* d_out, int out_size) {
    const float* xyz  = (const float*)d_in[0];
    const int*   grid = (const int*)d_in[1];
    int N = in_sizes[0] / 3;
    float* out = (float*)d_out;

    pack_kernel<<<(N + 255) / 256, 256>>>(xyz, grid, N);

    dim3 g((N + 1023) / 1024, N);
    pair_kernel<<<g, 256>>>(out, N);
}

// round 15
// speedup vs baseline: 1.3723x; 1.0675x over previous
#include <cuda_runtime.h>
#include <math.h>

// ---------------------------------------------------------------------------
// N=3072 all-pairs mask/bucket kernel.
// Out sections (float32, concatenated): dxyz (N,N,3), buckets (N,N),
// dscanid (N,N), mask (N,N).
//
// R12 -> R13 (on top of the winning R10 layout: warp owns 128 consecutive j,
// smem-staged dxyz, coalesced scalar stores):
//   * SIMD byte-packed meta compares (vabsdiffu4+vcmpleu4) — kernel is now
//     issue/ALU-bound (issue 80.5%, alu 67.8%), this cuts ~16 ops/pair
//   * full-tile fast path hoisted (no per-t bounds predication)
//   * precomputed section base pointers / smem lane pointer
// ---------------------------------------------------------------------------

#define MAXN 8192
__device__ float4   g_P[MAXN];   // {x, y, z, cb_as_float}
__device__ unsigned g_X[MAXN];   // xb

// cb bytes: b0=c0, b1=c1, b2=c2, b3=blk
// xb bytes: b0=xc0+16, b1=xc1+16, b2=batch, b3=0
__global__ void pack_kernel(const float* __restrict__ xyz,
                            const int*   __restrict__ grid, int N) {
    int i = blockIdx.x * blockDim.x + threadIdx.x;
    if (i >= N) return;
    float x = xyz[3*i+0], y = xyz[3*i+1], z = xyz[3*i+2];
    int batch = grid[5*i+0], blk = grid[5*i+1];
    int c0 = grid[5*i+2], c1 = grid[5*i+3], c2 = grid[5*i+4];
    // xy_coarse = ceil(xyz[:, :2] / 3.0)  — pinned IEEE division
    int xc0 = (int)ceilf(__fdiv_rn(x, 3.0f));
    int xc1 = (int)ceilf(__fdiv_rn(y, 3.0f));
    unsigned cb = (unsigned)(c0 & 0xFF)
                | ((unsigned)(c1 & 0xFF) << 8)
                | ((unsigned)(c2 & 0xFF) << 16)
                | ((unsigned)(blk & 0xFF) << 24);
    unsigned xb = (unsigned)((xc0 + 16) & 0xFF)
                | ((unsigned)((xc1 + 16) & 0xFF) << 8)
                | ((unsigned)(batch & 0xFF) << 16);
    g_P[i] = make_float4(x, y, z, __uint_as_float(cb));
    g_X[i] = xb;
}

// bucket_base minus BETA: integer-valued float v, reference value = 8 + v.
__device__ __forceinline__ float bucket_v(float d) {
    float x  = d * 2.0f;            // x / RES, RES = 0.5 (exact)
    float xa = fabsf(x);
    if (xa <= 2.0f) {
        return rintf(x);            // round-half-even == jnp.round
    } else {
        float lr  = logf(xa * 0.5f) * 0.48089834696298783f; // 1/ln(8)
        float sup = fminf(rintf(2.0f - 6.0f * lr), 8.0f);
        return (x > 0.0f) ? sup : -sup;
    }
}

__global__ __launch_bounds__(256)
void pair_kernel(float* __restrict__ out, int N) {
    __shared__ float sdx[8][384];      // per-warp dxyz staging (1.5 KB each)

    int warp = threadIdx.x >> 5;
    int lane = threadIdx.x & 31;
    int i    = blockIdx.y;
    int j0w  = blockIdx.x * 1024 + warp * 128;   // warp's 128-wide j base
    if (j0w >= N) return;
    bool full = (j0w + 128 <= N);

    float4 pi = g_P[i];
    unsigned cbi = __float_as_uint(pi.w);
    unsigned xbi = g_X[i];
    int bi = (int)(cbi >> 24);
    int si = bi >> 1;   // scanid_i

    size_t NN   = (size_t)N * (size_t)N;
    size_t rowb = (size_t)i * (size_t)N + (size_t)j0w;
    float* outB = out + 3*NN + rowb;   // buckets row base
    float* outD = out + 4*NN + rowb;   // dscanid row base
    float* outM = out + 5*NN + rowb;   // mask row base
    float* sw   = &sdx[warp][lane * 3];

    if (full) {
#pragma unroll
        for (int t = 0; t < 4; t++) {
            int jl = t * 32 + lane;
            float4   pj  = g_P[j0w + jl];
            unsigned cbj = __float_as_uint(pj.w);
            unsigned xbj = g_X[j0w + jl];

            // forcekeep: coord bytes absdiff<=1, blk byte diff==0
            unsigned v1 = __vcmpleu4(__vabsdiffu4(cbi, cbj), 0x00010101u);
            bool forcekeep = (v1 == 0xFFFFFFFFu);
            // v2: bytes0,1 coarse-adj, byte2 batch-eq, byte3 trivially true
            unsigned v2 = __vcmpleu4(__vabsdiffu4(xbi, xbj), 0x00000101u);
            bool kc_batch = (v2 == 0xFFFFFFFFu);     // batch_eq & keep_coarse
            bool batch_eq = (v2 & 0x00FF0000u) != 0u;

            int  bj       = (int)(cbj >> 24);
            bool block_le = (bi <= bj);

            float dx = pi.x - pj.x, dy = pi.y - pj.y, dz = pi.z - pj.z;
            bool keepr = (dx*dx + dy*dy + dz*dz) <= 9.0f;

            // == batch_eq & block_le & (fk|kc) & (fk|keepr)
            bool mask = block_le & ((forcekeep & batch_eq) | (kc_batch & keepr));

            sw[t*96 + 0] = mask ? dx : 0.0f;
            sw[t*96 + 1] = mask ? dy : 0.0f;
            sw[t*96 + 2] = mask ? dz : 0.0f;

            // sparse + warp-coherent: divergent bucket path wins
            int b = 0, ds = 0;
            if (mask) {
                b = 289 * (8 + (int)bucket_v(dx))
                  +  17 * (8 + (int)bucket_v(dy))
                  +        (8 + (int)bucket_v(dz));
                ds = (bj >> 1) - si;
            }
            outB[jl] = (float)b;
            outD[jl] = (float)ds;
            outM[jl] = mask ? 1.0f : 0.0f;
        }

        __syncwarp();

        // dxyz: 384 consecutive floats per warp -> 3 contiguous float4 bursts
        const float4* src = reinterpret_cast<const float4*>(sdx[warp]);
        float4* dst = reinterpret_cast<float4*>(out + rowb * 3);
        dst[lane]      = src[lane];
        dst[lane + 32] = src[lane + 32];
        dst[lane + 64] = src[lane + 64];
    } else {
        // generic tail path (not taken at N=3072)
#pragma unroll
        for (int t = 0; t < 4; t++) {
            int jl = t * 32 + lane;
            int j  = j0w + jl;
            bool inb = (j < N);
            float4   pj  = g_P[inb ? j : 0];
            unsigned cbj = __float_as_uint(pj.w);
            unsigned xbj = g_X[inb ? j : 0];

            unsigned v1 = __vcmpleu4(__vabsdiffu4(cbi, cbj), 0x00010101u);
            bool forcekeep = (v1 == 0xFFFFFFFFu);
            unsigned v2 = __vcmpleu4(__vabsdiffu4(xbi, xbj), 0x00000101u);
            bool kc_batch = (v2 == 0xFFFFFFFFu);
            bool batch_eq = (v2 & 0x00FF0000u) != 0u;

            int  bj       = (int)(cbj >> 24);
            bool block_le = (bi <= bj);

            float dx = pi.x - pj.x, dy = pi.y - pj.y, dz = pi.z - pj.z;
            bool keepr = (dx*dx + dy*dy + dz*dz) <= 9.0f;

            bool mask = block_le & ((forcekeep & batch_eq) | (kc_batch & keepr)) & inb;

            sw[t*96 + 0] = mask ? dx : 0.0f;
            sw[t*96 + 1] = mask ? dy : 0.0f;
            sw[t*96 + 2] = mask ? dz : 0.0f;

            int b = 0, ds = 0;
            if (mask) {
                b = 289 * (8 + (int)bucket_v(dx))
                  +  17 * (8 + (int)bucket_v(dy))
                  +        (8 + (int)bucket_v(dz));
                ds = (bj >> 1) - si;
            }
            if (inb) {
                outB[jl] = (float)b;
                outD[jl] = (float)ds;
                outM[jl] = mask ? 1.0f : 0.0f;
            }
        }

        __syncwarp();

        int nrem = (N - j0w) * 3;      // floats in this partial tile
        for (int k = lane; k < nrem; k += 32)
            out[rowb * 3 + k] = sdx[warp][k];
    }
}

extern "C" void kernel_launch(void* const* d_in, const int* in_sizes, int n_in,
                              void* d_out, int out_size) {
    const float* xyz  = (const float*)d_in[0];
    const int*   grid = (const int*)d_in[1];
    int N = in_sizes[0] / 3;
    float* out = (float*)d_out;

    pack_kernel<<<(N + 255) / 256, 256>>>(xyz, grid, N);

    dim3 g((N + 1023) / 1024, N);
    pair_kernel<<<g, 256>>>(out, N);
}